// round 15
// baseline (speedup 1.0000x reference)
#include <cuda_runtime.h>
#include <cuda_fp16.h>
#include <stdint.h>

#define NB 2
#define CD 256
#define LL 4096
#define NH 4
#define DKH 64

static constexpr float LOG2E = 1.4426950408889634f;

__device__ float  g_x  [NB * LL * CD];        // residual: [b][l][c] fp32
__device__ __half g_xh [NB * LL * CD];        // x hi (fp16)
__device__ __half g_xl [NB * LL * CD];        // x lo (fp16)
__device__ __half g_v  [NB * NH * LL * DKH];  // q/k/v heads (fp16)
__device__ __half g_ath[NB * LL * CD];        // attn out hi
__device__ __half g_atl[NB * LL * CD];        // attn out lo
__device__ __half g_wqh[CD * CD];             // w_qkv hi/lo
__device__ __half g_wql[CD * CD];
__device__ __half g_fwh[CD * CD];             // fc_w hi/lo
__device__ __half g_fwl[CD * CD];
__device__ float  g_norm[NB * NH * LL];       // per-row |q|
__device__ int    g_gmax[NB * NH];            // per-(b,h) max |q| (int bits)

// ------------------------- helpers -------------------------
__device__ __forceinline__ uint32_t smem_u32(const void* p) {
    uint32_t a;
    asm("{ .reg .u64 t; cvta.to.shared.u64 t, %1; cvt.u32.u64 %0, t; }"
        : "=r"(a) : "l"(p));
    return a;
}
__device__ __forceinline__ uint32_t SWZ(uint32_t o) {
    return o ^ ((o >> 3) & 0x70);
}
__device__ __forceinline__ void ldsm4(uint32_t* r, uint32_t a) {
    asm volatile("ldmatrix.sync.aligned.m8n8.x4.shared.b16 {%0,%1,%2,%3}, [%4];"
                 : "=r"(r[0]), "=r"(r[1]), "=r"(r[2]), "=r"(r[3]) : "r"(a));
}
__device__ __forceinline__ void ldsm4t(uint32_t* r, uint32_t a) {
    asm volatile("ldmatrix.sync.aligned.m8n8.x4.trans.shared.b16 {%0,%1,%2,%3}, [%4];"
                 : "=r"(r[0]), "=r"(r[1]), "=r"(r[2]), "=r"(r[3]) : "r"(a));
}
__device__ __forceinline__ void mma_f16(float* d, const uint32_t* a,
                                        uint32_t b0, uint32_t b1) {
    asm volatile(
        "mma.sync.aligned.m16n8k16.row.col.f32.f16.f16.f32 "
        "{%0,%1,%2,%3}, {%4,%5,%6,%7}, {%8,%9}, {%0,%1,%2,%3};"
        : "+f"(d[0]), "+f"(d[1]), "+f"(d[2]), "+f"(d[3])
        : "r"(a[0]), "r"(a[1]), "r"(a[2]), "r"(a[3]), "r"(b0), "r"(b1));
}
__device__ __forceinline__ void mma_f16s(float* d, uint32_t a0, uint32_t a1,
                                         uint32_t a2, uint32_t a3,
                                         uint32_t b0, uint32_t b1) {
    asm volatile(
        "mma.sync.aligned.m16n8k16.row.col.f32.f16.f16.f32 "
        "{%0,%1,%2,%3}, {%4,%5,%6,%7}, {%8,%9}, {%0,%1,%2,%3};"
        : "+f"(d[0]), "+f"(d[1]), "+f"(d[2]), "+f"(d[3])
        : "r"(a0), "r"(a1), "r"(a2), "r"(a3), "r"(b0), "r"(b1));
}
__device__ __forceinline__ float ex2f(float x) {
    float y;
    asm("ex2.approx.ftz.f32 %0, %1;" : "=f"(y) : "f"(x));
    return y;
}
__device__ __forceinline__ uint32_t pk_h2(float a, float b) {
    __half2 h = __floats2half2_rn(a, b);
    return *(uint32_t*)&h;
}
__device__ __forceinline__ void cpa16(uint32_t s, const void* g) {
    asm volatile("cp.async.cg.shared.global [%0], [%1], 16;" :: "r"(s), "l"(g));
}
__device__ __forceinline__ void cpa_commit() {
    asm volatile("cp.async.commit_group;" ::: "memory");
}
template <int N>
__device__ __forceinline__ void cpa_wait() {
    asm volatile("cp.async.wait_group %0;" :: "n"(N) : "memory");
}

// ---------------------------------------------------------------------------
// Kernel 0a: transpose input -> g_x (fp32) + g_xh/g_xl (fp16 hi/lo)
// ---------------------------------------------------------------------------
__global__ __launch_bounds__(256) void k_prep(const float* __restrict__ qin) {
    __shared__ float T[64][65];
    const int bt = blockIdx.z, c0 = blockIdx.y * 64, l0 = blockIdx.x * 64;
    const int tid = threadIdx.x;
    #pragma unroll
    for (int i = 0; i < 16; i++) {
        int idx = tid + i * 256;
        int ci = idx >> 6, lj = idx & 63;
        T[ci][lj] = qin[(size_t)bt * CD * LL + (size_t)(c0 + ci) * LL + l0 + lj];
    }
    __syncthreads();
    #pragma unroll
    for (int i = 0; i < 16; i++) {
        int idx = tid + i * 256;
        int li = idx >> 6, cj = idx & 63;
        float v = T[cj][li];
        size_t o = (size_t)(bt * LL + l0 + li) * CD + c0 + cj;
        g_x[o] = v;
        __half h = __float2half_rn(v);
        g_xh[o] = h;
        g_xl[o] = __float2half_rn(v - __half2float(h));
    }
}

// ---------------------------------------------------------------------------
// Kernel 0b: convert weights to fp16 hi/lo + reset gmax
// ---------------------------------------------------------------------------
__global__ __launch_bounds__(256) void k_prep_w(const float* __restrict__ wq,
                                                const float* __restrict__ fw) {
    int idx = blockIdx.x * 256 + threadIdx.x;   // 65536 total
    if (idx < NB * NH) g_gmax[idx] = 0;
    float v = wq[idx];
    __half h = __float2half_rn(v);
    g_wqh[idx] = h;
    g_wql[idx] = __float2half_rn(v - __half2float(h));
    float u = fw[idx];
    __half g = __float2half_rn(u);
    g_fwh[idx] = g;
    g_fwl[idx] = __float2half_rn(u - __half2float(g));
}

// ---------------------------------------------------------------------------
// GEMM mainloop for qkv: M=128 x N=64 x K=256, fp16 hi/lo 3-MMA, pure cp.async.
// ---------------------------------------------------------------------------
__device__ __forceinline__ void gemm_ml(const char* gah, const char* gal,
                                        const char* gbh, const char* gbl,
                                        uint32_t base, int tid, int wid,
                                        uint32_t laneRow, uint32_t laneCol,
                                        float (&acc)[8][4]) {
    auto pref = [&](int kc) {
        uint32_t st = base + (uint32_t)(kc & 1) * 49152u;
        #pragma unroll
        for (int i = 0; i < 4; i++) {             // A: 1024 chunks
            int idx = tid + i * 256;
            int r = idx >> 3, c8 = idx & 7;
            uint32_t so = SWZ(r * 128 + c8 * 16);
            size_t go = (size_t)r * 512 + (size_t)kc * 128 + c8 * 16;
            cpa16(st + so, gah + go);
            cpa16(st + 16384 + so, gal + go);
        }
        #pragma unroll
        for (int i = 0; i < 2; i++) {             // B: 512 chunks
            int idx = tid + i * 256;
            int r = idx >> 3, c8 = idx & 7;
            uint32_t so = SWZ(r * 128 + c8 * 16);
            size_t go = (size_t)r * 512 + (size_t)kc * 128 + c8 * 16;
            cpa16(st + 32768 + so, gbh + go);
            cpa16(st + 40960 + so, gbl + go);
        }
    };
    pref(0); cpa_commit();
    pref(1); cpa_commit();
    #pragma unroll
    for (int kc = 0; kc < 4; kc++) {
        if (kc < 3) cpa_wait<1>(); else cpa_wait<0>();
        __syncthreads();
        uint32_t sb = base + (uint32_t)(kc & 1) * 49152u;
        #pragma unroll
        for (int s = 0; s < 4; s++) {
            uint32_t ah[4], al[4];
            uint32_t offA = SWZ((wid * 16 + laneRow) * 128 + s * 32 + laneCol);
            ldsm4(ah, sb + offA);
            ldsm4(al, sb + 16384 + offA);
            #pragma unroll
            for (int nf = 0; nf < 4; nf++) {
                uint32_t offB = SWZ((nf * 16 + laneRow) * 128 + s * 32 + laneCol);
                uint32_t b4[4], c4[4];
                ldsm4(b4, sb + 32768 + offB);
                ldsm4(c4, sb + 40960 + offB);
                mma_f16(acc[2 * nf],     ah, b4[0], b4[2]);
                mma_f16(acc[2 * nf],     al, b4[0], b4[2]);
                mma_f16(acc[2 * nf],     ah, c4[0], c4[2]);
                mma_f16(acc[2 * nf + 1], ah, b4[1], b4[3]);
                mma_f16(acc[2 * nf + 1], al, b4[1], b4[3]);
                mma_f16(acc[2 * nf + 1], ah, c4[1], c4[3]);
            }
        }
        __syncthreads();
        if (kc + 2 < 4) { pref(kc + 2); cpa_commit(); }
    }
}

// ---------------------------------------------------------------------------
// Kernel 1: QKV projection (HMMA) -> g_v fp16 + row norms + per-(b,h) max
// ---------------------------------------------------------------------------
__global__ __launch_bounds__(256, 2) void k_qkv_mma() {
    extern __shared__ char smg[];
    const uint32_t base = smem_u32(smg);
    const int tid = threadIdx.x, lane = tid & 31, wid = tid >> 5;
    const int m0 = blockIdx.x * 128;
    const int h = blockIdx.y, bt = blockIdx.z, bh = bt * NH + h;
    const uint32_t laneRow = lane & 15;
    const uint32_t laneCol = ((lane >> 4) & 1) * 16;

    float acc[8][4] = {};
    gemm_ml((const char*)(g_xh + (size_t)(bt * LL + m0) * CD),
            (const char*)(g_xl + (size_t)(bt * LL + m0) * CD),
            (const char*)(g_wqh + (size_t)h * 64 * CD),
            (const char*)(g_wql + (size_t)h * 64 * CD),
            base, tid, wid, laneRow, laneCol, acc);

    __half* gv = g_v + (size_t)bh * LL * DKH;
    const int r = m0 + wid * 16 + (lane >> 2);
    const int cb = (lane & 3) * 2;
    float s0 = 0.f, s1 = 0.f;
    #pragma unroll
    for (int f = 0; f < 8; f++) {
        int c = f * 8 + cb;
        *(uint32_t*)&gv[(size_t)r * DKH + c] = pk_h2(acc[f][0], acc[f][1]);
        *(uint32_t*)&gv[(size_t)(r + 8) * DKH + c] = pk_h2(acc[f][2], acc[f][3]);
        s0 += acc[f][0] * acc[f][0] + acc[f][1] * acc[f][1];
        s1 += acc[f][2] * acc[f][2] + acc[f][3] * acc[f][3];
    }
    s0 += __shfl_xor_sync(0xffffffffu, s0, 1);
    s0 += __shfl_xor_sync(0xffffffffu, s0, 2);
    s1 += __shfl_xor_sync(0xffffffffu, s1, 1);
    s1 += __shfl_xor_sync(0xffffffffu, s1, 2);
    if ((lane & 3) == 0) {
        float n0 = sqrtf(s0), n1 = sqrtf(s1);
        g_norm[(size_t)bh * LL + r] = n0;
        g_norm[(size_t)bh * LL + r + 8] = n1;
        atomicMax(&g_gmax[bh], __float_as_int(fmaxf(n0, n1)));
    }
}

// ---------------------------------------------------------------------------
// Kernel 2: HMMA flash attention (R13 best config).
// 128 threads / 4 warps; warp owns 32 q-rows (2 m-frags); CTA = 128 rows;
// half-tile (64-col) softmax chunks; 3-stage KV ring + 16KB Q = 64KB; occ 2.
// Fixed per-row exp shift via Q==K Cauchy-Schwarz bound.
// ---------------------------------------------------------------------------
__device__ __forceinline__ void prefetch_kv(uint32_t buf, const char* g, int tid) {
    #pragma unroll
    for (int i = 0; i < 8; i++) {
        int c = tid + i * 128;
        int n = c >> 3, c8 = c & 7;
        uint32_t go = n * 128 + c8 * 16;
        cpa16(buf + SWZ(go), g + go);
    }
}

__global__ __launch_bounds__(128, 2) void k_attn_mma() {
    extern __shared__ char sm[];
    const uint32_t base = smem_u32(sm);

    const int tid = threadIdx.x;
    const int lane = tid & 31;
    const int wid = tid >> 5;
    const int bh = blockIdx.y;
    const int m0 = blockIdx.x * 128;

    const char* gvb = (const char*)(g_v + (size_t)bh * LL * DKH);

    const uint32_t laneRow = lane & 15;
    const uint32_t laneCol = ((lane >> 4) & 1) * 16;

    const uint32_t Qb = base + 49152;   // 16KB Q staging after 3x16KB ring

    #pragma unroll
    for (int i = 0; i < 8; i++) {
        int c = tid + i * 128;
        int n = c >> 3, c8 = c & 7;
        cpa16(Qb + SWZ(n * 128 + c8 * 16), gvb + (m0 + n) * 128 + c8 * 16);
    }
    cpa_commit();
    prefetch_kv(base, gvb, tid);
    cpa_commit();
    prefetch_kv(base + 16384, gvb + 16384, tid);
    cpa_commit();

    cpa_wait<2>();
    __syncthreads();

    uint32_t qh[2][4][4];
    #pragma unroll
    for (int mi = 0; mi < 2; mi++) {
        uint32_t rowb = (wid * 32 + mi * 16 + laneRow) * 128;
        #pragma unroll
        for (int c = 0; c < 4; c++)
            ldsm4(qh[mi][c], Qb + SWZ(rowb + c * 32 + laneCol));
    }

    const float c1 = LOG2E * 0.125f;
    const int rbase = m0 + wid * 32 + (lane >> 2);
    const float gmax = __int_as_float(g_gmax[bh]);
    float mc[2][2];
    #pragma unroll
    for (int mi = 0; mi < 2; mi++) {
        mc[mi][0] = g_norm[(size_t)bh * LL + rbase + mi * 16] * gmax * c1;
        mc[mi][1] = g_norm[(size_t)bh * LL + rbase + mi * 16 + 8] * gmax * c1;
    }

    float o[2][8][4] = {};
    float l[2][2] = {};

    const int NT = LL / 128;
    for (int t = 0; t < NT; t++) {
        const uint32_t KVb = base + (uint32_t)(t % 3) * 16384;

        if (t + 1 < NT) cpa_wait<1>(); else cpa_wait<0>();
        __syncthreads();
        if (t + 2 < NT) {
            prefetch_kv(base + (uint32_t)((t + 2) % 3) * 16384,
                        gvb + (size_t)(t + 2) * 16384, tid);
            cpa_commit();
        }

        #pragma unroll
        for (int hf = 0; hf < 2; hf++) {
            const int nb = hf * 64;

            float s[2][8][4];
            #pragma unroll
            for (int mi = 0; mi < 2; mi++)
                #pragma unroll
                for (int j = 0; j < 8; j++)
                    #pragma unroll
                    for (int k = 0; k < 4; k++) s[mi][j][k] = 0.f;

            #pragma unroll
            for (int jp = 0; jp < 4; jp++) {
                #pragma unroll
                for (int c = 0; c < 4; c++) {
                    uint32_t off = SWZ((nb + jp * 16 + laneRow) * 128 +
                                       c * 32 + laneCol);
                    uint32_t bv[4];
                    ldsm4(bv, KVb + off);
                    mma_f16(s[0][2 * jp],     qh[0][c], bv[0], bv[2]);
                    mma_f16(s[0][2 * jp + 1], qh[0][c], bv[1], bv[3]);
                    mma_f16(s[1][2 * jp],     qh[1][c], bv[0], bv[2]);
                    mma_f16(s[1][2 * jp + 1], qh[1][c], bv[1], bv[3]);
                }
            }

            uint32_t p[2][8][2];
            #pragma unroll
            for (int mi = 0; mi < 2; mi++) {
                #pragma unroll
                for (int j = 0; j < 8; j++) {
                    float e0 = ex2f(fmaf(s[mi][j][0], c1, -mc[mi][0]));
                    float e1 = ex2f(fmaf(s[mi][j][1], c1, -mc[mi][0]));
                    float e2 = ex2f(fmaf(s[mi][j][2], c1, -mc[mi][1]));
                    float e3 = ex2f(fmaf(s[mi][j][3], c1, -mc[mi][1]));
                    l[mi][0] += e0 + e1;
                    l[mi][1] += e2 + e3;
                    p[mi][j][0] = pk_h2(e0, e1);
                    p[mi][j][1] = pk_h2(e2, e3);
                }
            }

            #pragma unroll
            for (int c = 0; c < 4; c++) {
                #pragma unroll
                for (int vp = 0; vp < 4; vp++) {
                    uint32_t off = SWZ((nb + c * 16 + laneRow) * 128 +
                                       vp * 32 + laneCol);
                    uint32_t bv[4];
                    ldsm4t(bv, KVb + off);
                    mma_f16s(o[0][2 * vp], p[0][2 * c][0], p[0][2 * c][1],
                             p[0][2 * c + 1][0], p[0][2 * c + 1][1],
                             bv[0], bv[1]);
                    mma_f16s(o[0][2 * vp + 1], p[0][2 * c][0], p[0][2 * c][1],
                             p[0][2 * c + 1][0], p[0][2 * c + 1][1],
                             bv[2], bv[3]);
                    mma_f16s(o[1][2 * vp], p[1][2 * c][0], p[1][2 * c][1],
                             p[1][2 * c + 1][0], p[1][2 * c + 1][1],
                             bv[0], bv[1]);
                    mma_f16s(o[1][2 * vp + 1], p[1][2 * c][0], p[1][2 * c][1],
                             p[1][2 * c + 1][0], p[1][2 * c + 1][1],
                             bv[2], bv[3]);
                }
            }
        }
        __syncthreads();
    }

    #pragma unroll
    for (int mi = 0; mi < 2; mi++) {
        #pragma unroll
        for (int hsel = 0; hsel < 2; hsel++) {
            l[mi][hsel] += __shfl_xor_sync(0xffffffffu, l[mi][hsel], 1);
            l[mi][hsel] += __shfl_xor_sync(0xffffffffu, l[mi][hsel], 2);
        }
    }
    const int b = bh >> 2, hd = bh & 3;
    const int cb = (lane & 3) * 2;
    #pragma unroll
    for (int mi = 0; mi < 2; mi++) {
        const float inv0 = 1.f / l[mi][0], inv1 = 1.f / l[mi][1];
        const int r0 = rbase + mi * 16;
        #pragma unroll
        for (int vt = 0; vt < 8; vt++) {
            size_t i0 = (size_t)(b * LL + r0) * CD + hd * 64 + vt * 8 + cb;
            size_t i1 = (size_t)(b * LL + r0 + 8) * CD + hd * 64 + vt * 8 + cb;
            float v00 = o[mi][vt][0] * inv0, v01 = o[mi][vt][1] * inv0;
            float v10 = o[mi][vt][2] * inv1, v11 = o[mi][vt][3] * inv1;
            __half h00 = __float2half_rn(v00), h01 = __float2half_rn(v01);
            __half h10 = __float2half_rn(v10), h11 = __float2half_rn(v11);
            __half2 hh0; hh0.x = h00; hh0.y = h01;
            __half2 hh1; hh1.x = h10; hh1.y = h11;
            *(uint32_t*)&g_ath[i0] = *(uint32_t*)&hh0;
            *(uint32_t*)&g_ath[i1] = *(uint32_t*)&hh1;
            *(uint32_t*)&g_atl[i0] =
                pk_h2(v00 - __half2float(h00), v01 - __half2float(h01));
            *(uint32_t*)&g_atl[i1] =
                pk_h2(v10 - __half2float(h10), v11 - __half2float(h11));
        }
    }
}

// ---------------------------------------------------------------------------
// Kernel 3: fused fc GEMM + bias + residual + LayerNorm -> d_out.
// CTA = 128 rows x ALL 256 out-cols, K=256 in 4 chunks of 64 (2-stage smem:
// per stage A hi/lo 32KB + B hi/lo 64KB = 96KB). 8 warps x 16 rows.
// Each warp ends holding full rows -> LN via 2 shuffles, write d_out.
// ---------------------------------------------------------------------------
__global__ __launch_bounds__(256, 1) void k_fc_ln(const float* __restrict__ fb,
                                                  const float* __restrict__ gam,
                                                  const float* __restrict__ bet,
                                                  float* __restrict__ out) {
    extern __shared__ char smg[];
    const uint32_t base = smem_u32(smg);
    const int tid = threadIdx.x, lane = tid & 31, wid = tid >> 5;
    const int m0 = blockIdx.x * 128;     // row in [0, B*L)
    const uint32_t laneRow = lane & 15;
    const uint32_t laneCol = ((lane >> 4) & 1) * 16;

    const char* gah = (const char*)(g_ath + (size_t)m0 * CD);
    const char* gal = (const char*)(g_atl + (size_t)m0 * CD);
    const char* gbh = (const char*)g_fwh;
    const char* gbl = (const char*)g_fwl;

    // stage layout: Ah[0,16K) Al[16K,32K) Bh[32K,64K) Bl[64K,96K); stride 96K
    auto pref = [&](int kc) {
        uint32_t st = base + (uint32_t)(kc & 1) * 98304u;
        #pragma unroll
        for (int i = 0; i < 4; i++) {             // A: 1024 chunks
            int idx = tid + i * 256;
            int r = idx >> 3, c8 = idx & 7;
            uint32_t so = SWZ(r * 128 + c8 * 16);
            size_t go = (size_t)r * 512 + (size_t)kc * 128 + c8 * 16;
            cpa16(st + so, gah + go);
            cpa16(st + 16384 + so, gal + go);
        }
        #pragma unroll
        for (int i = 0; i < 8; i++) {             // B: 2048 chunks (256 rows)
            int idx = tid + i * 256;
            int r = idx >> 3, c8 = idx & 7;
            uint32_t so = SWZ(r * 128 + c8 * 16);
            size_t go = (size_t)r * 512 + (size_t)kc * 128 + c8 * 16;
            cpa16(st + 32768 + so, gbh + go);
            cpa16(st + 65536 + so, gbl + go);
        }
    };

    float acc[32][4] = {};
    pref(0); cpa_commit();
    pref(1); cpa_commit();
    #pragma unroll
    for (int kc = 0; kc < 4; kc++) {
        if (kc < 3) cpa_wait<1>(); else cpa_wait<0>();
        __syncthreads();
        uint32_t sb = base + (uint32_t)(kc & 1) * 98304u;
        #pragma unroll
        for (int s = 0; s < 4; s++) {
            uint32_t ah[4], al[4];
            uint32_t offA = SWZ((wid * 16 + laneRow) * 128 + s * 32 + laneCol);
            ldsm4(ah, sb + offA);
            ldsm4(al, sb + 16384 + offA);
            #pragma unroll
            for (int nf = 0; nf < 16; nf++) {
                uint32_t offB = SWZ((nf * 16 + laneRow) * 128 + s * 32 + laneCol);
                uint32_t b4[4], c4[4];
                ldsm4(b4, sb + 32768 + offB);
                ldsm4(c4, sb + 65536 + offB);
                mma_f16(acc[2 * nf],     ah, b4[0], b4[2]);
                mma_f16(acc[2 * nf],     al, b4[0], b4[2]);
                mma_f16(acc[2 * nf],     ah, c4[0], c4[2]);
                mma_f16(acc[2 * nf + 1], ah, b4[1], b4[3]);
                mma_f16(acc[2 * nf + 1], al, b4[1], b4[3]);
                mma_f16(acc[2 * nf + 1], ah, c4[1], c4[3]);
            }
        }
        __syncthreads();
        if (kc + 2 < 4) { pref(kc + 2); cpa_commit(); }
    }

    // ---- epilogue: bias + residual, then LayerNorm per full row ----
    const int r0 = m0 + wid * 16 + (lane >> 2);   // row A
    const int r1 = r0 + 8;                        // row B
    const int cb = (lane & 3) * 2;
    float s0 = 0.f, q0 = 0.f, s1 = 0.f, q1 = 0.f;
    #pragma unroll
    for (int f = 0; f < 32; f++) {
        int c = f * 8 + cb;
        float b0 = fb[c], b1 = fb[c + 1];
        float2 res0 = *(const float2*)&g_x[(size_t)r0 * CD + c];
        float2 res1 = *(const float2*)&g_x[(size_t)r1 * CD + c];
        acc[f][0] += b0 + res0.x;
        acc[f][1] += b1 + res0.y;
        acc[f][2] += b0 + res1.x;
        acc[f][3] += b1 + res1.y;
        s0 += acc[f][0] + acc[f][1];
        q0 += acc[f][0] * acc[f][0] + acc[f][1] * acc[f][1];
        s1 += acc[f][2] + acc[f][3];
        q1 += acc[f][2] * acc[f][2] + acc[f][3] * acc[f][3];
    }
    s0 += __shfl_xor_sync(0xffffffffu, s0, 1);
    s0 += __shfl_xor_sync(0xffffffffu, s0, 2);
    q0 += __shfl_xor_sync(0xffffffffu, q0, 1);
    q0 += __shfl_xor_sync(0xffffffffu, q0, 2);
    s1 += __shfl_xor_sync(0xffffffffu, s1, 1);
    s1 += __shfl_xor_sync(0xffffffffu, s1, 2);
    q1 += __shfl_xor_sync(0xffffffffu, q1, 1);
    q1 += __shfl_xor_sync(0xffffffffu, q1, 2);
    const float mu0 = s0 * (1.f / CD);
    const float rs0 = rsqrtf(q0 * (1.f / CD) - mu0 * mu0 + 1e-5f);
    const float mu1 = s1 * (1.f / CD);
    const float rs1 = rsqrtf(q1 * (1.f / CD) - mu1 * mu1 + 1e-5f);
    #pragma unroll
    for (int f = 0; f < 32; f++) {
        int c = f * 8 + cb;
        float g0 = gam[c], g1 = gam[c + 1];
        float t0 = bet[c], t1 = bet[c + 1];
        *(float2*)&out[(size_t)r0 * CD + c] =
            make_float2((acc[f][0] - mu0) * rs0 * g0 + t0,
                        (acc[f][1] - mu0) * rs0 * g1 + t1);
        *(float2*)&out[(size_t)r1 * CD + c] =
            make_float2((acc[f][2] - mu1) * rs1 * g0 + t0,
                        (acc[f][3] - mu1) * rs1 * g1 + t1);
    }
}

// ---------------------------------------------------------------------------
extern "C" void kernel_launch(void* const* d_in, const int* in_sizes, int n_in,
                              void* d_out, int out_size) {
    const float* qin = (const float*)d_in[0];
    const float* wq  = (const float*)d_in[1];
    const float* fw  = (const float*)d_in[2];
    const float* fb  = (const float*)d_in[3];
    const float* lg  = (const float*)d_in[4];
    const float* lb  = (const float*)d_in[5];
    float* out = (float*)d_out;

    const int attn_smem = 65536;    // 3 x 16KB ring + 16KB Q
    const int gemm_smem = 98304;    // 2 x 48KB (qkv)
    const int fcln_smem = 196608;   // 2 x 96KB (fused fc+ln)
    cudaFuncSetAttribute(k_attn_mma,
                         cudaFuncAttributeMaxDynamicSharedMemorySize, attn_smem);
    cudaFuncSetAttribute(k_qkv_mma,
                         cudaFuncAttributeMaxDynamicSharedMemorySize, gemm_smem);
    cudaFuncSetAttribute(k_fc_ln,
                         cudaFuncAttributeMaxDynamicSharedMemorySize, fcln_smem);

    k_prep<<<dim3(LL / 64, CD / 64, NB), 256>>>(qin);
    k_prep_w<<<CD * CD / 256, 256>>>(wq, fw);
    k_qkv_mma<<<dim3(LL / 128, NH, NB), 256, gemm_smem>>>();
    k_attn_mma<<<dim3(LL / 128, NB * NH), 128, attn_smem>>>();
    k_fc_ln<<<NB * LL / 128, 256, fcln_smem>>>(fb, lg, lb, out);
}

// round 16
// speedup vs baseline: 1.1108x; 1.1108x over previous
#include <cuda_runtime.h>
#include <cuda_fp16.h>
#include <stdint.h>

#define NB 2
#define CD 256
#define LL 4096
#define NH 4
#define DKH 64

static constexpr float LOG2E = 1.4426950408889634f;

__device__ float  g_x  [NB * LL * CD];        // residual: [b][l][c] fp32
__device__ __half g_xh [NB * LL * CD];        // x hi (fp16)
__device__ __half g_xl [NB * LL * CD];        // x lo (fp16)
__device__ __half g_v  [NB * NH * LL * DKH];  // q/k/v heads (fp16)
__device__ __half g_ath[NB * LL * CD];        // attn out (fp16)
__device__ float  g_y  [NB * LL * CD];        // fc+residual
__device__ __half g_wqh[CD * CD];             // w_qkv hi/lo
__device__ __half g_wql[CD * CD];
__device__ __half g_fwh[CD * CD];             // fc_w (fp16)
__device__ float  g_norm[NB * NH * LL];       // per-row |q|
__device__ int    g_gmax[NB * NH];            // per-(b,h) max |q| (int bits)

// ------------------------- helpers -------------------------
__device__ __forceinline__ uint32_t smem_u32(const void* p) {
    uint32_t a;
    asm("{ .reg .u64 t; cvta.to.shared.u64 t, %1; cvt.u32.u64 %0, t; }"
        : "=r"(a) : "l"(p));
    return a;
}
__device__ __forceinline__ uint32_t SWZ(uint32_t o) {
    return o ^ ((o >> 3) & 0x70);
}
__device__ __forceinline__ void ldsm4(uint32_t* r, uint32_t a) {
    asm volatile("ldmatrix.sync.aligned.m8n8.x4.shared.b16 {%0,%1,%2,%3}, [%4];"
                 : "=r"(r[0]), "=r"(r[1]), "=r"(r[2]), "=r"(r[3]) : "r"(a));
}
__device__ __forceinline__ void ldsm4t(uint32_t* r, uint32_t a) {
    asm volatile("ldmatrix.sync.aligned.m8n8.x4.trans.shared.b16 {%0,%1,%2,%3}, [%4];"
                 : "=r"(r[0]), "=r"(r[1]), "=r"(r[2]), "=r"(r[3]) : "r"(a));
}
__device__ __forceinline__ void mma_f16(float* d, const uint32_t* a,
                                        uint32_t b0, uint32_t b1) {
    asm volatile(
        "mma.sync.aligned.m16n8k16.row.col.f32.f16.f16.f32 "
        "{%0,%1,%2,%3}, {%4,%5,%6,%7}, {%8,%9}, {%0,%1,%2,%3};"
        : "+f"(d[0]), "+f"(d[1]), "+f"(d[2]), "+f"(d[3])
        : "r"(a[0]), "r"(a[1]), "r"(a[2]), "r"(a[3]), "r"(b0), "r"(b1));
}
__device__ __forceinline__ void mma_f16s(float* d, uint32_t a0, uint32_t a1,
                                         uint32_t a2, uint32_t a3,
                                         uint32_t b0, uint32_t b1) {
    asm volatile(
        "mma.sync.aligned.m16n8k16.row.col.f32.f16.f16.f32 "
        "{%0,%1,%2,%3}, {%4,%5,%6,%7}, {%8,%9}, {%0,%1,%2,%3};"
        : "+f"(d[0]), "+f"(d[1]), "+f"(d[2]), "+f"(d[3])
        : "r"(a0), "r"(a1), "r"(a2), "r"(a3), "r"(b0), "r"(b1));
}
__device__ __forceinline__ float ex2f(float x) {
    float y;
    asm("ex2.approx.ftz.f32 %0, %1;" : "=f"(y) : "f"(x));
    return y;
}
__device__ __forceinline__ uint32_t pk_h2(float a, float b) {
    __half2 h = __floats2half2_rn(a, b);
    return *(uint32_t*)&h;
}
__device__ __forceinline__ void cpa16(uint32_t s, const void* g) {
    asm volatile("cp.async.cg.shared.global [%0], [%1], 16;" :: "r"(s), "l"(g));
}
__device__ __forceinline__ void cpa_commit() {
    asm volatile("cp.async.commit_group;" ::: "memory");
}
template <int N>
__device__ __forceinline__ void cpa_wait() {
    asm volatile("cp.async.wait_group %0;" :: "n"(N) : "memory");
}

// ---------------------------------------------------------------------------
// Kernel 0a: transpose input -> g_x (fp32) + g_xh/g_xl (fp16 hi/lo)
// ---------------------------------------------------------------------------
__global__ __launch_bounds__(256) void k_prep(const float* __restrict__ qin) {
    __shared__ float T[64][65];
    const int bt = blockIdx.z, c0 = blockIdx.y * 64, l0 = blockIdx.x * 64;
    const int tid = threadIdx.x;
    #pragma unroll
    for (int i = 0; i < 16; i++) {
        int idx = tid + i * 256;
        int ci = idx >> 6, lj = idx & 63;
        T[ci][lj] = qin[(size_t)bt * CD * LL + (size_t)(c0 + ci) * LL + l0 + lj];
    }
    __syncthreads();
    #pragma unroll
    for (int i = 0; i < 16; i++) {
        int idx = tid + i * 256;
        int li = idx >> 6, cj = idx & 63;
        float v = T[cj][li];
        size_t o = (size_t)(bt * LL + l0 + li) * CD + c0 + cj;
        g_x[o] = v;
        __half h = __float2half_rn(v);
        g_xh[o] = h;
        g_xl[o] = __float2half_rn(v - __half2float(h));
    }
}

// ---------------------------------------------------------------------------
// Kernel 0b: weights -> fp16 (wq hi/lo, fc single) + reset gmax
// ---------------------------------------------------------------------------
__global__ __launch_bounds__(256) void k_prep_w(const float* __restrict__ wq,
                                                const float* __restrict__ fw) {
    int idx = blockIdx.x * 256 + threadIdx.x;   // 65536 total
    if (idx < NB * NH) g_gmax[idx] = 0;
    float v = wq[idx];
    __half h = __float2half_rn(v);
    g_wqh[idx] = h;
    g_wql[idx] = __float2half_rn(v - __half2float(h));
    g_fwh[idx] = __float2half_rn(fw[idx]);
}

// ---------------------------------------------------------------------------
// qkv GEMM mainloop: M=128 x N=64 x K=256, fp16 hi/lo 3-MMA, pure cp.async.
// ---------------------------------------------------------------------------
__device__ __forceinline__ void gemm_ml(const char* gah, const char* gal,
                                        const char* gbh, const char* gbl,
                                        uint32_t base, int tid, int wid,
                                        uint32_t laneRow, uint32_t laneCol,
                                        float (&acc)[8][4]) {
    auto pref = [&](int kc) {
        uint32_t st = base + (uint32_t)(kc & 1) * 49152u;
        #pragma unroll
        for (int i = 0; i < 4; i++) {             // A: 1024 chunks
            int idx = tid + i * 256;
            int r = idx >> 3, c8 = idx & 7;
            uint32_t so = SWZ(r * 128 + c8 * 16);
            size_t go = (size_t)r * 512 + (size_t)kc * 128 + c8 * 16;
            cpa16(st + so, gah + go);
            cpa16(st + 16384 + so, gal + go);
        }
        #pragma unroll
        for (int i = 0; i < 2; i++) {             // B: 512 chunks
            int idx = tid + i * 256;
            int r = idx >> 3, c8 = idx & 7;
            uint32_t so = SWZ(r * 128 + c8 * 16);
            size_t go = (size_t)r * 512 + (size_t)kc * 128 + c8 * 16;
            cpa16(st + 32768 + so, gbh + go);
            cpa16(st + 40960 + so, gbl + go);
        }
    };
    pref(0); cpa_commit();
    pref(1); cpa_commit();
    #pragma unroll
    for (int kc = 0; kc < 4; kc++) {
        if (kc < 3) cpa_wait<1>(); else cpa_wait<0>();
        __syncthreads();
        uint32_t sb = base + (uint32_t)(kc & 1) * 49152u;
        #pragma unroll
        for (int s = 0; s < 4; s++) {
            uint32_t ah[4], al[4];
            uint32_t offA = SWZ((wid * 16 + laneRow) * 128 + s * 32 + laneCol);
            ldsm4(ah, sb + offA);
            ldsm4(al, sb + 16384 + offA);
            #pragma unroll
            for (int nf = 0; nf < 4; nf++) {
                uint32_t offB = SWZ((nf * 16 + laneRow) * 128 + s * 32 + laneCol);
                uint32_t b4[4], c4[4];
                ldsm4(b4, sb + 32768 + offB);
                ldsm4(c4, sb + 40960 + offB);
                mma_f16(acc[2 * nf],     ah, b4[0], b4[2]);
                mma_f16(acc[2 * nf],     al, b4[0], b4[2]);
                mma_f16(acc[2 * nf],     ah, c4[0], c4[2]);
                mma_f16(acc[2 * nf + 1], ah, b4[1], b4[3]);
                mma_f16(acc[2 * nf + 1], al, b4[1], b4[3]);
                mma_f16(acc[2 * nf + 1], ah, c4[1], c4[3]);
            }
        }
        __syncthreads();
        if (kc + 2 < 4) { pref(kc + 2); cpa_commit(); }
    }
}

// ---------------------------------------------------------------------------
// Kernel 1: QKV projection (HMMA) -> g_v fp16 + row norms + per-(b,h) max
// ---------------------------------------------------------------------------
__global__ __launch_bounds__(256, 2) void k_qkv_mma() {
    extern __shared__ char smg[];
    const uint32_t base = smem_u32(smg);
    const int tid = threadIdx.x, lane = tid & 31, wid = tid >> 5;
    const int m0 = blockIdx.x * 128;
    const int h = blockIdx.y, bt = blockIdx.z, bh = bt * NH + h;
    const uint32_t laneRow = lane & 15;
    const uint32_t laneCol = ((lane >> 4) & 1) * 16;

    float acc[8][4] = {};
    gemm_ml((const char*)(g_xh + (size_t)(bt * LL + m0) * CD),
            (const char*)(g_xl + (size_t)(bt * LL + m0) * CD),
            (const char*)(g_wqh + (size_t)h * 64 * CD),
            (const char*)(g_wql + (size_t)h * 64 * CD),
            base, tid, wid, laneRow, laneCol, acc);

    __half* gv = g_v + (size_t)bh * LL * DKH;
    const int r = m0 + wid * 16 + (lane >> 2);
    const int cb = (lane & 3) * 2;
    float s0 = 0.f, s1 = 0.f;
    #pragma unroll
    for (int f = 0; f < 8; f++) {
        int c = f * 8 + cb;
        *(uint32_t*)&gv[(size_t)r * DKH + c] = pk_h2(acc[f][0], acc[f][1]);
        *(uint32_t*)&gv[(size_t)(r + 8) * DKH + c] = pk_h2(acc[f][2], acc[f][3]);
        s0 += acc[f][0] * acc[f][0] + acc[f][1] * acc[f][1];
        s1 += acc[f][2] * acc[f][2] + acc[f][3] * acc[f][3];
    }
    s0 += __shfl_xor_sync(0xffffffffu, s0, 1);
    s0 += __shfl_xor_sync(0xffffffffu, s0, 2);
    s1 += __shfl_xor_sync(0xffffffffu, s1, 1);
    s1 += __shfl_xor_sync(0xffffffffu, s1, 2);
    if ((lane & 3) == 0) {
        float n0 = sqrtf(s0), n1 = sqrtf(s1);
        g_norm[(size_t)bh * LL + r] = n0;
        g_norm[(size_t)bh * LL + r + 8] = n1;
        atomicMax(&g_gmax[bh], __float_as_int(fmaxf(n0, n1)));
    }
}

// ---------------------------------------------------------------------------
// Kernel 2: HMMA flash attention (R13 best config, hi-only epilogue).
// ---------------------------------------------------------------------------
__device__ __forceinline__ void prefetch_kv(uint32_t buf, const char* g, int tid) {
    #pragma unroll
    for (int i = 0; i < 8; i++) {
        int c = tid + i * 128;
        int n = c >> 3, c8 = c & 7;
        uint32_t go = n * 128 + c8 * 16;
        cpa16(buf + SWZ(go), g + go);
    }
}

__global__ __launch_bounds__(128, 2) void k_attn_mma() {
    extern __shared__ char sm[];
    const uint32_t base = smem_u32(sm);

    const int tid = threadIdx.x;
    const int lane = tid & 31;
    const int wid = tid >> 5;
    const int bh = blockIdx.y;
    const int m0 = blockIdx.x * 128;

    const char* gvb = (const char*)(g_v + (size_t)bh * LL * DKH);

    const uint32_t laneRow = lane & 15;
    const uint32_t laneCol = ((lane >> 4) & 1) * 16;

    const uint32_t Qb = base + 49152;   // 16KB Q staging after 3x16KB ring

    #pragma unroll
    for (int i = 0; i < 8; i++) {
        int c = tid + i * 128;
        int n = c >> 3, c8 = c & 7;
        cpa16(Qb + SWZ(n * 128 + c8 * 16), gvb + (m0 + n) * 128 + c8 * 16);
    }
    cpa_commit();
    prefetch_kv(base, gvb, tid);
    cpa_commit();
    prefetch_kv(base + 16384, gvb + 16384, tid);
    cpa_commit();

    cpa_wait<2>();
    __syncthreads();

    uint32_t qh[2][4][4];
    #pragma unroll
    for (int mi = 0; mi < 2; mi++) {
        uint32_t rowb = (wid * 32 + mi * 16 + laneRow) * 128;
        #pragma unroll
        for (int c = 0; c < 4; c++)
            ldsm4(qh[mi][c], Qb + SWZ(rowb + c * 32 + laneCol));
    }

    const float c1 = LOG2E * 0.125f;
    const int rbase = m0 + wid * 32 + (lane >> 2);
    const float gmax = __int_as_float(g_gmax[bh]);
    float mc[2][2];
    #pragma unroll
    for (int mi = 0; mi < 2; mi++) {
        mc[mi][0] = g_norm[(size_t)bh * LL + rbase + mi * 16] * gmax * c1;
        mc[mi][1] = g_norm[(size_t)bh * LL + rbase + mi * 16 + 8] * gmax * c1;
    }

    float o[2][8][4] = {};
    float l[2][2] = {};

    const int NT = LL / 128;
    for (int t = 0; t < NT; t++) {
        const uint32_t KVb = base + (uint32_t)(t % 3) * 16384;

        if (t + 1 < NT) cpa_wait<1>(); else cpa_wait<0>();
        __syncthreads();
        if (t + 2 < NT) {
            prefetch_kv(base + (uint32_t)((t + 2) % 3) * 16384,
                        gvb + (size_t)(t + 2) * 16384, tid);
            cpa_commit();
        }

        #pragma unroll
        for (int hf = 0; hf < 2; hf++) {
            const int nb = hf * 64;

            float s[2][8][4];
            #pragma unroll
            for (int mi = 0; mi < 2; mi++)
                #pragma unroll
                for (int j = 0; j < 8; j++)
                    #pragma unroll
                    for (int k = 0; k < 4; k++) s[mi][j][k] = 0.f;

            #pragma unroll
            for (int jp = 0; jp < 4; jp++) {
                #pragma unroll
                for (int c = 0; c < 4; c++) {
                    uint32_t off = SWZ((nb + jp * 16 + laneRow) * 128 +
                                       c * 32 + laneCol);
                    uint32_t bv[4];
                    ldsm4(bv, KVb + off);
                    mma_f16(s[0][2 * jp],     qh[0][c], bv[0], bv[2]);
                    mma_f16(s[0][2 * jp + 1], qh[0][c], bv[1], bv[3]);
                    mma_f16(s[1][2 * jp],     qh[1][c], bv[0], bv[2]);
                    mma_f16(s[1][2 * jp + 1], qh[1][c], bv[1], bv[3]);
                }
            }

            uint32_t p[2][8][2];
            #pragma unroll
            for (int mi = 0; mi < 2; mi++) {
                #pragma unroll
                for (int j = 0; j < 8; j++) {
                    float e0 = ex2f(fmaf(s[mi][j][0], c1, -mc[mi][0]));
                    float e1 = ex2f(fmaf(s[mi][j][1], c1, -mc[mi][0]));
                    float e2 = ex2f(fmaf(s[mi][j][2], c1, -mc[mi][1]));
                    float e3 = ex2f(fmaf(s[mi][j][3], c1, -mc[mi][1]));
                    l[mi][0] += e0 + e1;
                    l[mi][1] += e2 + e3;
                    p[mi][j][0] = pk_h2(e0, e1);
                    p[mi][j][1] = pk_h2(e2, e3);
                }
            }

            #pragma unroll
            for (int c = 0; c < 4; c++) {
                #pragma unroll
                for (int vp = 0; vp < 4; vp++) {
                    uint32_t off = SWZ((nb + c * 16 + laneRow) * 128 +
                                       vp * 32 + laneCol);
                    uint32_t bv[4];
                    ldsm4t(bv, KVb + off);
                    mma_f16s(o[0][2 * vp], p[0][2 * c][0], p[0][2 * c][1],
                             p[0][2 * c + 1][0], p[0][2 * c + 1][1],
                             bv[0], bv[1]);
                    mma_f16s(o[0][2 * vp + 1], p[0][2 * c][0], p[0][2 * c][1],
                             p[0][2 * c + 1][0], p[0][2 * c + 1][1],
                             bv[2], bv[3]);
                    mma_f16s(o[1][2 * vp], p[1][2 * c][0], p[1][2 * c][1],
                             p[1][2 * c + 1][0], p[1][2 * c + 1][1],
                             bv[0], bv[1]);
                    mma_f16s(o[1][2 * vp + 1], p[1][2 * c][0], p[1][2 * c][1],
                             p[1][2 * c + 1][0], p[1][2 * c + 1][1],
                             bv[2], bv[3]);
                }
            }
        }
        __syncthreads();
    }

    #pragma unroll
    for (int mi = 0; mi < 2; mi++) {
        #pragma unroll
        for (int hsel = 0; hsel < 2; hsel++) {
            l[mi][hsel] += __shfl_xor_sync(0xffffffffu, l[mi][hsel], 1);
            l[mi][hsel] += __shfl_xor_sync(0xffffffffu, l[mi][hsel], 2);
        }
    }
    const int b = bh >> 2, hd = bh & 3;
    const int cb = (lane & 3) * 2;
    #pragma unroll
    for (int mi = 0; mi < 2; mi++) {
        const float inv0 = 1.f / l[mi][0], inv1 = 1.f / l[mi][1];
        const int r0 = rbase + mi * 16;
        #pragma unroll
        for (int vt = 0; vt < 8; vt++) {
            size_t i0 = (size_t)(b * LL + r0) * CD + hd * 64 + vt * 8 + cb;
            size_t i1 = (size_t)(b * LL + r0 + 8) * CD + hd * 64 + vt * 8 + cb;
            *(uint32_t*)&g_ath[i0] = pk_h2(o[mi][vt][0] * inv0,
                                           o[mi][vt][1] * inv0);
            *(uint32_t*)&g_ath[i1] = pk_h2(o[mi][vt][2] * inv1,
                                           o[mi][vt][3] * inv1);
        }
    }
}

// ---------------------------------------------------------------------------
// Kernel 3: fc GEMM (single fp16 HMMA) + bias + residual -> g_y fp32.
// M=128 x N=64 x K=256; stage = A 16K + B 8K = 24K, 2 stages = 48K; occ 2.
// ---------------------------------------------------------------------------
__global__ __launch_bounds__(256, 2) void k_fc_mma(const float* __restrict__ fb) {
    extern __shared__ char smg[];
    const uint32_t base = smem_u32(smg);
    const int tid = threadIdx.x, lane = tid & 31, wid = tid >> 5;
    const int m0 = blockIdx.x * 128;     // row in [0, B*L)
    const int o0 = blockIdx.y * 64;
    const uint32_t laneRow = lane & 15;
    const uint32_t laneCol = ((lane >> 4) & 1) * 16;

    const char* ga = (const char*)(g_ath + (size_t)m0 * CD);
    const char* gb = (const char*)(g_fwh + (size_t)o0 * CD);

    auto pref = [&](int kc) {
        uint32_t st = base + (uint32_t)(kc & 1) * 24576u;
        #pragma unroll
        for (int i = 0; i < 4; i++) {             // A: 1024 chunks
            int idx = tid + i * 256;
            int r = idx >> 3, c8 = idx & 7;
            uint32_t so = SWZ(r * 128 + c8 * 16);
            size_t go = (size_t)r * 512 + (size_t)kc * 128 + c8 * 16;
            cpa16(st + so, ga + go);
        }
        #pragma unroll
        for (int i = 0; i < 2; i++) {             // B: 512 chunks
            int idx = tid + i * 256;
            int r = idx >> 3, c8 = idx & 7;
            uint32_t so = SWZ(r * 128 + c8 * 16);
            size_t go = (size_t)r * 512 + (size_t)kc * 128 + c8 * 16;
            cpa16(st + 16384 + so, gb + go);
        }
    };

    float acc[8][4] = {};
    pref(0); cpa_commit();
    pref(1); cpa_commit();
    #pragma unroll
    for (int kc = 0; kc < 4; kc++) {
        if (kc < 3) cpa_wait<1>(); else cpa_wait<0>();
        __syncthreads();
        uint32_t sb = base + (uint32_t)(kc & 1) * 24576u;
        #pragma unroll
        for (int s = 0; s < 4; s++) {
            uint32_t ah[4];
            uint32_t offA = SWZ((wid * 16 + laneRow) * 128 + s * 32 + laneCol);
            ldsm4(ah, sb + offA);
            #pragma unroll
            for (int nf = 0; nf < 4; nf++) {
                uint32_t offB = SWZ((nf * 16 + laneRow) * 128 + s * 32 + laneCol);
                uint32_t b4[4];
                ldsm4(b4, sb + 16384 + offB);
                mma_f16(acc[2 * nf],     ah, b4[0], b4[2]);
                mma_f16(acc[2 * nf + 1], ah, b4[1], b4[3]);
            }
        }
        __syncthreads();
        if (kc + 2 < 4) { pref(kc + 2); cpa_commit(); }
    }

    const int r = m0 + wid * 16 + (lane >> 2);
    const int cb = (lane & 3) * 2;
    #pragma unroll
    for (int f = 0; f < 8; f++) {
        int c = o0 + f * 8 + cb;
        float b0 = fb[c], b1 = fb[c + 1];
        float2 res0 = *(const float2*)&g_x[(size_t)r * CD + c];
        float2 res1 = *(const float2*)&g_x[(size_t)(r + 8) * CD + c];
        *(float2*)&g_y[(size_t)r * CD + c] =
            make_float2(acc[f][0] + b0 + res0.x, acc[f][1] + b1 + res0.y);
        *(float2*)&g_y[(size_t)(r + 8) * CD + c] =
            make_float2(acc[f][2] + b0 + res1.x, acc[f][3] + b1 + res1.y);
    }
}

// ---------------------------------------------------------------------------
// Kernel 4: LayerNorm over C=256
// ---------------------------------------------------------------------------
__global__ __launch_bounds__(256) void k_ln(const float* __restrict__ gam,
                                            const float* __restrict__ bet,
                                            float* __restrict__ out) {
    const int row = blockIdx.x * 8 + (threadIdx.x >> 5);
    const int lane = threadIdx.x & 31;
    const float* y = g_y + (size_t)row * CD;
    float v[8], s = 0.f, s2 = 0.f;
    #pragma unroll
    for (int k = 0; k < 8; k++) {
        v[k] = y[lane + 32 * k];
        s += v[k];
        s2 += v[k] * v[k];
    }
    #pragma unroll
    for (int off = 16; off; off >>= 1) {
        s  += __shfl_xor_sync(0xffffffffu, s, off);
        s2 += __shfl_xor_sync(0xffffffffu, s2, off);
    }
    const float mu = s * (1.f / CD);
    const float rstd = rsqrtf(s2 * (1.f / CD) - mu * mu + 1e-5f);
    #pragma unroll
    for (int k = 0; k < 8; k++) {
        int c = lane + 32 * k;
        out[(size_t)row * CD + c] = (v[k] - mu) * rstd * gam[c] + bet[c];
    }
}

// ---------------------------------------------------------------------------
extern "C" void kernel_launch(void* const* d_in, const int* in_sizes, int n_in,
                              void* d_out, int out_size) {
    const float* qin = (const float*)d_in[0];
    const float* wq  = (const float*)d_in[1];
    const float* fw  = (const float*)d_in[2];
    const float* fb  = (const float*)d_in[3];
    const float* lg  = (const float*)d_in[4];
    const float* lb  = (const float*)d_in[5];
    float* out = (float*)d_out;

    const int attn_smem = 65536;   // 3 x 16KB ring + 16KB Q
    const int qkv_smem  = 98304;   // 2 x 48KB
    const int fc_smem   = 49152;   // 2 x 24KB
    cudaFuncSetAttribute(k_attn_mma,
                         cudaFuncAttributeMaxDynamicSharedMemorySize, attn_smem);
    cudaFuncSetAttribute(k_qkv_mma,
                         cudaFuncAttributeMaxDynamicSharedMemorySize, qkv_smem);
    cudaFuncSetAttribute(k_fc_mma,
                         cudaFuncAttributeMaxDynamicSharedMemorySize, fc_smem);

    k_prep<<<dim3(LL / 64, CD / 64, NB), 256>>>(qin);
    k_prep_w<<<CD * CD / 256, 256>>>(wq, fw);
    k_qkv_mma<<<dim3(LL / 128, NH, NB), 256, qkv_smem>>>();
    k_attn_mma<<<dim3(LL / 128, NB * NH), 128, attn_smem>>>();
    k_fc_mma<<<dim3(NB * LL / 128, CD / 64), 256, fc_smem>>>(fb);
    k_ln<<<NB * LL / 8, 256>>>(lg, lb, out);
}